// round 11
// baseline (speedup 1.0000x reference)
#include <cuda_runtime.h>
#include <cuda_bf16.h>
#include <cuda_fp16.h>

#define BB 4
#define PP 512
#define KK 4
#define HH 200
#define WW 336
#define AA 14
#define PS 56
#define SCALE 0.25f
#define NTHREADS 224   /* 4 rows x 56 cols */
#define NROWITER 14    /* 56 / 4 */

#define HP (HH + 1)    /* padded height */
#define WP (WW + 1)    /* padded width  */

#define LOG2E 1.4426950408889634f

__device__ __forceinline__ float ex2f(float x) {
    float r; asm("ex2.approx.f32 %0,%1;" : "=f"(r) : "f"(x)); return r;
}

// bases transposed to fp16 with x-difference (R8 layout):
// g_basesH[b][y][x] = { h2(f_k0,f_k1), h2(f_k2,f_k3), h2(d_k0,d_k1), h2(d_k2,d_k3) }
// where f = feat(y,x), d = feat(y,x+1) - feat(y,x)  (0 in pad region)
__device__ uint4 g_basesH[BB * HP * WP];

__global__ __launch_bounds__(256)
void transpose_bases_kernel(const float* __restrict__ bases)
{
    int i = blockIdx.x * blockDim.x + threadIdx.x;   // over B*HP*WP
    if (i >= BB * HP * WP) return;
    int b  = i / (HP * WP);
    int yx = i - b * (HP * WP);
    int y  = yx / WP;
    int x  = yx - y * WP;

    const float* base = bases + (size_t)b * (KK * HH * WW);
    float4 v0 = make_float4(0.f, 0.f, 0.f, 0.f);
    float4 v1 = make_float4(0.f, 0.f, 0.f, 0.f);
    if (y < HH && x < WW) {
        const float* p = base + y * WW + x;
        v0 = make_float4(p[0], p[HH * WW], p[2 * HH * WW], p[3 * HH * WW]);
        if (x + 1 < WW) {
            const float* q = p + 1;
            v1 = make_float4(q[0], q[HH * WW], q[2 * HH * WW], q[3 * HH * WW]);
        }
    }
    half2 hf0 = __floats2half2_rn(v0.x, v0.y);
    half2 hf1 = __floats2half2_rn(v0.z, v0.w);
    half2 hd0 = __floats2half2_rn(v1.x - v0.x, v1.y - v0.y);
    half2 hd1 = __floats2half2_rn(v1.z - v0.z, v1.w - v0.w);
    uint4 o;
    o.x = *(unsigned int*)&hf0;
    o.y = *(unsigned int*)&hf1;
    o.z = *(unsigned int*)&hd0;
    o.w = *(unsigned int*)&hd1;
    g_basesH[i] = o;
}

__global__ __launch_bounds__(NTHREADS, 8)
void Blender_38809324486930_kernel(const float* __restrict__ boxes,
                                   const float* __restrict__ attn,
                                   float* __restrict__ out)
{
    const int bp = blockIdx.x;           // 0 .. B*P-1
    const int b  = bp >> 9;              // P = 512

    __shared__ float s_attnT[AA * AA * KK];      // [ay][ax][k], pre-scaled by log2e
    __shared__ float s_rowv[PS * AA * KK];       // [oy][j][k]
    __shared__ float4 s_ylut[PS];                // {ybase(int), ly, vy, rbbase(int)}

    const int tid = threadIdx.x;
    const int ox  = tid % PS;            // fixed column per thread
    const int r0  = tid / PS;            // starting row (0..3)

    // ---- load attention tile transposed to [ay][ax][k], scaled by log2e ----
    {
        const float* ap = attn + (size_t)bp * (KK * AA * AA);
        for (int i = tid; i < KK * AA * AA; i += NTHREADS) {
            int k  = i / (AA * AA);
            int yx = i - k * (AA * AA);
            s_attnT[yx * KK + k] = ap[i] * LOG2E;
        }
    }

    // ---- box (broadcast loads) ----
    const float bx1 = __ldg(&boxes[bp * 4 + 0]) * SCALE;
    const float by1 = __ldg(&boxes[bp * 4 + 1]) * SCALE;
    const float bx2 = __ldg(&boxes[bp * 4 + 2]) * SCALE;
    const float by2 = __ldg(&boxes[bp * 4 + 3]) * SCALE;
    const float bw = fmaxf(bx2 - bx1, 1.0f) * (1.0f / PS);
    const float bh = fmaxf(by2 - by1, 1.0f) * (1.0f / PS);

    const float resize_step = (float)(AA - 1) / (float)(PS - 1);

    // ---- y-state LUT: one float4 per output row ----
    if (tid >= 64 && tid < 64 + PS) {
        const int oy = tid - 64;
        const float sy = fmaf((float)oy + 0.5f, bh, by1);
        const float vy = (sy > -1.0f && sy < (float)HH) ? 1.0f : 0.0f;
        const float yc = fminf(fmaxf(sy, 0.0f), (float)(HH - 1));
        const int   y0 = (int)floorf(yc);
        const float ly = yc - (float)y0;
        float4 e;
        e.x = __int_as_float(y0 * WP);
        e.y = ly;
        e.z = vy;
        e.w = __int_as_float(oy * (AA * KK));
        s_ylut[oy] = e;
    }

    // ---- per-thread x state (registers, computed once) ----
    const float sx = bx1 + ((float)ox + 0.5f) * bw;
    const float vx = (sx > -1.0f && sx < (float)WW) ? 1.0f : 0.0f;
    const float xc = fminf(fmaxf(sx, 0.0f), (float)(WW - 1));
    const int   x0 = (int)floorf(xc);
    const float lx = xc - (float)x0;
    const half2 lx2 = __float2half2_rn(lx);

    const float srcx = (float)ox * resize_step;
    int ax0 = min(max((int)floorf(srcx), 0), AA - 2);
    const float txf = srcx - (float)ax0;
    const int axk = ax0 * KK;

    __syncthreads();

    // ---- precompute row-interpolated attention: rowv[oy][j][k] ----
    for (int e = tid; e < PS * AA; e += NTHREADS) {
        const int oy = e / AA;
        const int j  = e - oy * AA;
        const float srcy = (float)oy * resize_step;
        const int ay0 = min(max((int)floorf(srcy), 0), AA - 2);
        const float ty = srcy - (float)ay0;
        const float4 a0 = *(const float4*)&s_attnT[(ay0 * AA + j) * KK];
        const float4 a1 = *(const float4*)&s_attnT[((ay0 + 1) * AA + j) * KK];
        float4 rr;
        rr.x = a0.x + ty * (a1.x - a0.x);
        rr.y = a0.y + ty * (a1.y - a0.y);
        rr.z = a0.z + ty * (a1.z - a0.z);
        rr.w = a0.w + ty * (a1.w - a0.w);
        *(float4*)&s_rowv[e * KK] = rr;
    }
    __syncthreads();

    const uint4* __restrict__ fb = g_basesH + (size_t)b * (HP * WP);
    float* ob = out + (size_t)bp * (PS * PS) + tid;

    #pragma unroll 2
    for (int it = 0; it < NROWITER; it++) {
        const int oy = r0 + it * 4;

        // ---- per-row y state: one broadcast LDS.128 ----
        const float4 ys = s_ylut[oy];
        const int   ybase = __float_as_int(ys.x);
        const float ly    = ys.y;
        const float vmask = ys.z * vx;
        const int   rb    = __float_as_int(ys.w) + axk;

        // ---- RoIAlign: 2 x LDG.128; x-lerp in half2 (f + lx*d) ----
        const int i00 = ybase + x0;
        const uint4 t0 = __ldg(&fb[i00]);
        const uint4 t1 = __ldg(&fb[i00 + WP]);

        const half2 g0a = __hfma2(*(const half2*)&t0.z, lx2, *(const half2*)&t0.x);
        const half2 g0b = __hfma2(*(const half2*)&t0.w, lx2, *(const half2*)&t0.y);
        const half2 g1a = __hfma2(*(const half2*)&t1.z, lx2, *(const half2*)&t1.x);
        const half2 g1b = __hfma2(*(const half2*)&t1.w, lx2, *(const half2*)&t1.y);

        const float2 f0a = __half22float2(g0a);
        const float2 f0b = __half22float2(g0b);
        const float2 f1a = __half22float2(g1a);
        const float2 f1b = __half22float2(g1b);

        // ---- y-lerp in f32 ----
        float4 rv;
        rv.x = f0a.x + ly * (f1a.x - f0a.x);
        rv.y = f0a.y + ly * (f1a.y - f0a.y);
        rv.z = f0b.x + ly * (f1b.x - f0b.x);
        rv.w = f0b.y + ly * (f1b.y - f0b.y);

        // ---- attention column lerp ----
        const float4 a0 = *(const float4*)&s_rowv[rb];
        const float4 a1 = *(const float4*)&s_rowv[rb + KK];
        float4 a;
        a.x = a0.x + txf * (a1.x - a0.x);
        a.y = a0.y + txf * (a1.y - a0.y);
        a.z = a0.z + txf * (a1.z - a0.z);
        a.w = a0.w + txf * (a1.w - a0.w);

        // ---- softmax-blend in log2 domain (pivot on a.x; 3 ex2) ----
        const float e1 = ex2f(a.y - a.x);
        const float e2 = ex2f(a.z - a.x);
        const float e3 = ex2f(a.w - a.x);
        const float se  = 1.0f + e1 + e2 + e3;
        float acc = rv.x;
        acc = fmaf(e1, rv.y, acc);
        acc = fmaf(e2, rv.z, acc);
        acc = fmaf(e3, rv.w, acc);
        acc *= vmask;
        ob[it * NTHREADS] = __fdividef(acc, se);
    }
}

extern "C" void kernel_launch(void* const* d_in, const int* in_sizes, int n_in,
                              void* d_out, int out_size)
{
    const float* bases = (const float*)d_in[0];
    const float* boxes = (const float*)d_in[1];
    const float* attn  = (const float*)d_in[2];
    float* out = (float*)d_out;

    const int nT = BB * HP * WP;
    transpose_bases_kernel<<<(nT + 255) / 256, 256>>>(bases);
    Blender_38809324486930_kernel<<<BB * PP, NTHREADS>>>(boxes, attn, out);
}

// round 12
// speedup vs baseline: 1.0790x; 1.0790x over previous
#include <cuda_runtime.h>
#include <cuda_bf16.h>
#include <cuda_fp16.h>

#define BB 4
#define PP 512
#define KK 4
#define HH 200
#define WW 336
#define AA 14
#define PS 56
#define SCALE 0.25f
#define NTHREADS 224   /* 4 rows x 56 cols */
#define NROWITER 14    /* 56 / 4 */

#define HP (HH + 1)    /* padded height */
#define WP (WW + 1)    /* padded width  */

#define LOG2E 1.4426950408889634f

__device__ __forceinline__ float ex2f(float x) {
    float r; asm("ex2.approx.f32 %0,%1;" : "=f"(r) : "f"(x)); return r;
}

// bases transposed to fp16 with y-difference:
// g_basesH[b][y][x] = { h2(f_k0,f_k1), h2(f_k2,f_k3), h2(dy_k0,dy_k1), h2(dy_k2,dy_k3) }
// where f = feat(y,x), dy = feat(y+1,x) - feat(y,x)  (0 in pad region)
// => the two taps of a pixel are ADJACENT cells (x0, x0+1) in one row.
__device__ uint4 g_basesH[BB * HP * WP];

__device__ __forceinline__ float4 load_f4(const float* base, int y, int x)
{
    float4 v = make_float4(0.f, 0.f, 0.f, 0.f);
    if (y < HH && x < WW) {
        const float* p = base + y * WW + x;
        v = make_float4(p[0], p[HH * WW], p[2 * HH * WW], p[3 * HH * WW]);
    }
    return v;
}

__global__ __launch_bounds__(256)
void transpose_bases_kernel(const float* __restrict__ bases)
{
    int i = blockIdx.x * blockDim.x + threadIdx.x;   // over B*HP*WP
    if (i >= BB * HP * WP) return;
    int b  = i / (HP * WP);
    int yx = i - b * (HP * WP);
    int y  = yx / WP;
    int x  = yx - y * WP;

    const float* base = bases + (size_t)b * (KK * HH * WW);
    float4 v0 = load_f4(base, y, x);       // f(y, x)
    float4 v1 = load_f4(base, y + 1, x);   // f(y+1, x)

    half2 hf0 = __floats2half2_rn(v0.x, v0.y);
    half2 hf1 = __floats2half2_rn(v0.z, v0.w);
    half2 hd0 = __floats2half2_rn(v1.x - v0.x, v1.y - v0.y);
    half2 hd1 = __floats2half2_rn(v1.z - v0.z, v1.w - v0.w);
    uint4 o;
    o.x = *(unsigned int*)&hf0;
    o.y = *(unsigned int*)&hf1;
    o.z = *(unsigned int*)&hd0;
    o.w = *(unsigned int*)&hd1;
    g_basesH[i] = o;
}

__global__ __launch_bounds__(NTHREADS, 8)
void Blender_38809324486930_kernel(const float* __restrict__ boxes,
                                   const float* __restrict__ attn,
                                   float* __restrict__ out)
{
    const int bp = blockIdx.x;           // 0 .. B*P-1
    const int b  = bp >> 9;              // P = 512

    __shared__ float s_attnT[AA * AA * KK];      // [ay][ax][k], pre-scaled by log2e
    __shared__ float s_rowv[PS * AA * KK];       // [oy][j][k]

    const int tid = threadIdx.x;
    const int ox  = tid % PS;            // fixed column per thread
    const int r0  = tid / PS;            // starting row (0..3)

    // ---- load attention tile transposed to [ay][ax][k], scaled by log2e ----
    {
        const float* ap = attn + (size_t)bp * (KK * AA * AA);
        for (int i = tid; i < KK * AA * AA; i += NTHREADS) {
            int k  = i / (AA * AA);
            int yx = i - k * (AA * AA);
            s_attnT[yx * KK + k] = ap[i] * LOG2E;
        }
    }

    // ---- box (broadcast loads) ----
    const float bx1 = __ldg(&boxes[bp * 4 + 0]) * SCALE;
    const float by1 = __ldg(&boxes[bp * 4 + 1]) * SCALE;
    const float bx2 = __ldg(&boxes[bp * 4 + 2]) * SCALE;
    const float by2 = __ldg(&boxes[bp * 4 + 3]) * SCALE;
    const float bw = fmaxf(bx2 - bx1, 1.0f) * (1.0f / PS);
    const float bh = fmaxf(by2 - by1, 1.0f) * (1.0f / PS);

    const float resize_step = (float)(AA - 1) / (float)(PS - 1);

    // ---- per-thread x state (registers, computed once) ----
    const float sx = bx1 + ((float)ox + 0.5f) * bw;
    const float vx = (sx > -1.0f && sx < (float)WW) ? 1.0f : 0.0f;
    const float xc = fminf(fmaxf(sx, 0.0f), (float)(WW - 1));
    const int   x0 = (int)floorf(xc);
    const float lx = xc - (float)x0;

    const float srcx = (float)ox * resize_step;
    int ax0 = min(max((int)floorf(srcx), 0), AA - 2);
    const float txf = srcx - (float)ax0;
    const int axk = ax0 * KK;

    __syncthreads();

    // ---- precompute row-interpolated attention: rowv[oy][j][k] ----
    for (int e = tid; e < PS * AA; e += NTHREADS) {
        const int oy = e / AA;
        const int j  = e - oy * AA;
        const float srcy = (float)oy * resize_step;
        const int ay0 = min(max((int)floorf(srcy), 0), AA - 2);
        const float ty = srcy - (float)ay0;
        const float4 a0 = *(const float4*)&s_attnT[(ay0 * AA + j) * KK];
        const float4 a1 = *(const float4*)&s_attnT[((ay0 + 1) * AA + j) * KK];
        float4 rr;
        rr.x = a0.x + ty * (a1.x - a0.x);
        rr.y = a0.y + ty * (a1.y - a0.y);
        rr.z = a0.z + ty * (a1.z - a0.z);
        rr.w = a0.w + ty * (a1.w - a0.w);
        *(float4*)&s_rowv[e * KK] = rr;
    }
    __syncthreads();

    const uint4* __restrict__ fb = g_basesH + (size_t)b * (HP * WP);
    float* ob = out + (size_t)bp * (PS * PS) + tid;

    #pragma unroll 2
    for (int it = 0; it < NROWITER; it++) {
        const int oy = r0 + it * 4;

        // ---- per-row y state (registers) ----
        const float sy = fmaf((float)oy + 0.5f, bh, by1);
        const float vy = (sy > -1.0f && sy < (float)HH) ? 1.0f : 0.0f;
        const float yc = fminf(fmaxf(sy, 0.0f), (float)(HH - 1));
        const int   y0 = (int)floorf(yc);
        const float ly = yc - (float)y0;
        const half2 ly2 = __float2half2_rn(ly);
        const float vmask = vy * vx;

        // ---- RoIAlign: 2 ADJACENT LDG.128; y-lerp in half2 (f + ly*dy) ----
        const int i00 = y0 * WP + x0;
        const uint4 t0 = __ldg(&fb[i00]);        // column x0:   f | dy
        const uint4 t1 = __ldg(&fb[i00 + 1]);    // column x0+1: f | dy

        const half2 g0a = __hfma2(*(const half2*)&t0.z, ly2, *(const half2*)&t0.x);
        const half2 g0b = __hfma2(*(const half2*)&t0.w, ly2, *(const half2*)&t0.y);
        const half2 g1a = __hfma2(*(const half2*)&t1.z, ly2, *(const half2*)&t1.x);
        const half2 g1b = __hfma2(*(const half2*)&t1.w, ly2, *(const half2*)&t1.y);

        const float2 f0a = __half22float2(g0a);
        const float2 f0b = __half22float2(g0b);
        const float2 f1a = __half22float2(g1a);
        const float2 f1b = __half22float2(g1b);

        // ---- x-lerp in f32 ----
        float4 rv;
        rv.x = f0a.x + lx * (f1a.x - f0a.x);
        rv.y = f0a.y + lx * (f1a.y - f0a.y);
        rv.z = f0b.x + lx * (f1b.x - f0b.x);
        rv.w = f0b.y + lx * (f1b.y - f0b.y);

        // ---- attention column lerp ----
        const int rb = oy * (AA * KK) + axk;
        const float4 a0 = *(const float4*)&s_rowv[rb];
        const float4 a1 = *(const float4*)&s_rowv[rb + KK];
        float4 a;
        a.x = a0.x + txf * (a1.x - a0.x);
        a.y = a0.y + txf * (a1.y - a0.y);
        a.z = a0.z + txf * (a1.z - a0.z);
        a.w = a0.w + txf * (a1.w - a0.w);

        // ---- softmax-blend in log2 domain (pivot on a.x; 3 ex2) ----
        const float e1 = ex2f(a.y - a.x);
        const float e2 = ex2f(a.z - a.x);
        const float e3 = ex2f(a.w - a.x);
        const float se  = 1.0f + e1 + e2 + e3;
        float acc = rv.x;
        acc = fmaf(e1, rv.y, acc);
        acc = fmaf(e2, rv.z, acc);
        acc = fmaf(e3, rv.w, acc);
        acc *= vmask;                       // vmask folded once
        ob[it * NTHREADS] = __fdividef(acc, se);
    }
}

extern "C" void kernel_launch(void* const* d_in, const int* in_sizes, int n_in,
                              void* d_out, int out_size)
{
    const float* bases = (const float*)d_in[0];
    const float* boxes = (const float*)d_in[1];
    const float* attn  = (const float*)d_in[2];
    float* out = (float*)d_out;

    const int nT = BB * HP * WP;
    transpose_bases_kernel<<<(nT + 255) / 256, 256>>>(bases);
    Blender_38809324486930_kernel<<<BB * PP, NTHREADS>>>(boxes, attn, out);
}